// round 4
// baseline (speedup 1.0000x reference)
#include <cuda_runtime.h>

#define NB    8
#define CIN   3
#define NN    32768
#define COUT  128
#define NEDGE 4194304
#define NTOT  262144   // NB * NN

__device__ float  g_T0[NTOT * 4];
__device__ float  g_T1[NTOT * 4];
__device__ float  g_T2[NTOT * 4];
__device__ float  g_T3[NTOT * 4];
__device__ float  g_deg[NTOT];
__device__ float  g_dis[NTOT];
__device__ float  g_nw[NEDGE];
__device__ double g_mom[90];          // s[12] then upper-triangular M[78]
__device__ float  g_Wf[12 * COUT];    // BN-folded weights
__device__ float  g_bf[COUT];         // BN-folded bias

template <int K>
__device__ __forceinline__ float* T_ptr() {
    if (K == 0) return g_T0;
    if (K == 1) return g_T1;
    if (K == 2) return g_T2;
    return g_T3;
}

__device__ __forceinline__ void red_v4(float* addr, float a, float b, float c) {
    asm volatile("red.global.add.v4.f32 [%0], {%1, %2, %3, %4};"
                 :: "l"(addr), "f"(a), "f"(b), "f"(c), "f"(0.f) : "memory");
}

// ---------------------------------------------------------------------------
// 1) Build T0 = h (B,CIN,N)->(B*N, 3 padded to 4), zero deg/T1 and moments
// ---------------------------------------------------------------------------
__global__ void setup_kernel(const float* __restrict__ x) {
    int i = blockIdx.x * blockDim.x + threadIdx.x;
    if (i < NTOT) {
        int b = i >> 15;          // NN = 2^15
        int n = i & (NN - 1);
        const float* xb = x + (size_t)b * CIN * NN + n;
        float4 v;
        v.x = xb[0];
        v.y = xb[NN];
        v.z = xb[2 * NN];
        v.w = 0.f;
        reinterpret_cast<float4*>(g_T0)[i] = v;
        reinterpret_cast<float4*>(g_T1)[i] = make_float4(0.f, 0.f, 0.f, 0.f);
        g_deg[i] = 0.f;
    }
    if (blockIdx.x == 0 && threadIdx.x < 90) g_mom[threadIdx.x] = 0.0;
}

// ---------------------------------------------------------------------------
// 2) deg[src] += w   (self loops removed) — 2 edges/thread
// ---------------------------------------------------------------------------
__global__ void __launch_bounds__(256) deg_kernel(const int* __restrict__ ei,
                                                  const float* __restrict__ ew) {
    int base = (blockIdx.x * blockDim.x + threadIdx.x) * 2;
    int   s0 = ei[base],         s1 = ei[base + 1];
    int   d0 = ei[NEDGE + base], d1 = ei[NEDGE + base + 1];
    float w0 = ew[base],         w1 = ew[base + 1];
    if (s0 != d0 && w0 != 0.f) atomicAdd(&g_deg[s0], w0);
    if (s1 != d1 && w1 != 0.f) atomicAdd(&g_deg[s1], w1);
}

// ---------------------------------------------------------------------------
// 3) dis[i] = deg[i] > 0 ? rsqrt(deg[i]) : 0   (node pass, tiny)
// ---------------------------------------------------------------------------
__global__ void dis_kernel() {
    int i = blockIdx.x * blockDim.x + threadIdx.x;
    if (i >= NTOT) return;
    float d = g_deg[i];
    g_dis[i] = (d > 0.f) ? rsqrtf(fmaxf(d, 1e-12f)) : 0.f;
}

// ---------------------------------------------------------------------------
// 4) Init a T buffer:  dst = -src
// ---------------------------------------------------------------------------
template <int KDST, int KSRC>
__global__ void initT_kernel() {
    int i = blockIdx.x * blockDim.x + threadIdx.x;
    if (i >= NTOT) return;
    float4 v = reinterpret_cast<const float4*>(T_ptr<KSRC>())[i];
    reinterpret_cast<float4*>(T_ptr<KDST>())[i] = make_float4(-v.x, -v.y, -v.z, 0.f);
}

// ---------------------------------------------------------------------------
// 5a) Fused norm + first prop: nw[e] = -dis[s] w dis[d]; T1[d] += nw * T0[s]
//     4 edges/thread, loads front-batched for MLP
// ---------------------------------------------------------------------------
__global__ void __launch_bounds__(256) norm_prop_kernel(const int* __restrict__ ei,
                                                        const float* __restrict__ ew) {
    int base = (blockIdx.x * blockDim.x + threadIdx.x) * 4;

    int s[4], d[4];
    float w[4];
    #pragma unroll
    for (int j = 0; j < 4; j++) {
        s[j] = ei[base + j];
        d[j] = ei[NEDGE + base + j];
        w[j] = ew[base + j];
    }

    float is[4], id[4];
    float4 t[4];
    #pragma unroll
    for (int j = 0; j < 4; j++) {
        is[j] = __ldg(&g_dis[s[j]]);
        id[j] = __ldg(&g_dis[d[j]]);
        t[j]  = __ldg(reinterpret_cast<const float4*>(g_T0) + s[j]);
    }

    float nw[4];
    #pragma unroll
    for (int j = 0; j < 4; j++) {
        nw[j] = (s[j] == d[j]) ? 0.f : -is[j] * w[j] * id[j];
        g_nw[base + j] = nw[j];
    }

    #pragma unroll
    for (int j = 0; j < 4; j++)
        if (nw[j] != 0.f)
            red_v4(g_T1 + 4 * (size_t)d[j], nw[j] * t[j].x, nw[j] * t[j].y, nw[j] * t[j].z);
}

// ---------------------------------------------------------------------------
// 5b) Scatter: tout[dst] += SCALE * nw[e] * tin[src]  — 4 edges/thread
// ---------------------------------------------------------------------------
template <int KIN, int KOUT, int SCALE>
__global__ void __launch_bounds__(256) prop_kernel(const int* __restrict__ ei) {
    const float* tin = T_ptr<KIN>();
    float* tout = T_ptr<KOUT>();
    int base = (blockIdx.x * blockDim.x + threadIdx.x) * 4;

    int s[4], d[4];
    float nw[4];
    #pragma unroll
    for (int j = 0; j < 4; j++) {
        s[j]  = ei[base + j];
        d[j]  = ei[NEDGE + base + j];
        nw[j] = g_nw[base + j] * (float)SCALE;
    }

    float4 t[4];
    #pragma unroll
    for (int j = 0; j < 4; j++)
        t[j] = __ldg(reinterpret_cast<const float4*>(tin) + s[j]);

    #pragma unroll
    for (int j = 0; j < 4; j++)
        if (nw[j] != 0.f)
            red_v4(tout + 4 * (size_t)d[j], nw[j] * t[j].x, nw[j] * t[j].y, nw[j] * t[j].z);
}

// ---------------------------------------------------------------------------
// 6) Moments: s[12] = sum t,  M[78] = upper-tri of sum t t^T
// ---------------------------------------------------------------------------
__device__ __forceinline__ float warp_sum(float v) {
    #pragma unroll
    for (int o = 16; o > 0; o >>= 1) v += __shfl_down_sync(0xFFFFFFFFu, v, o);
    return v;
}

__global__ void __launch_bounds__(256) moments_kernel() {
    float s[12];
    float m[78];
    #pragma unroll
    for (int j = 0; j < 12; j++) s[j] = 0.f;
    #pragma unroll
    for (int j = 0; j < 78; j++) m[j] = 0.f;

    int stride = gridDim.x * blockDim.x;
    for (int i = blockIdx.x * blockDim.x + threadIdx.x; i < NTOT; i += stride) {
        float4 a = reinterpret_cast<const float4*>(g_T0)[i];
        float4 b = reinterpret_cast<const float4*>(g_T1)[i];
        float4 c = reinterpret_cast<const float4*>(g_T2)[i];
        float4 d = reinterpret_cast<const float4*>(g_T3)[i];
        float t[12] = {a.x, a.y, a.z, b.x, b.y, b.z, c.x, c.y, c.z, d.x, d.y, d.z};
        #pragma unroll
        for (int f = 0; f < 12; f++) s[f] += t[f];
        int idx = 0;
        #pragma unroll
        for (int f = 0; f < 12; f++) {
            #pragma unroll
            for (int g = f; g < 12; g++) {
                m[idx] += t[f] * t[g];
                idx++;
            }
        }
    }

    __shared__ float blk[90];
    if (threadIdx.x < 90) blk[threadIdx.x] = 0.f;
    __syncthreads();
    #pragma unroll
    for (int v = 0; v < 12; v++) {
        float val = warp_sum(s[v]);
        if ((threadIdx.x & 31) == 0) atomicAdd(&blk[v], val);
    }
    #pragma unroll
    for (int v = 0; v < 78; v++) {
        float val = warp_sum(m[v]);
        if ((threadIdx.x & 31) == 0) atomicAdd(&blk[12 + v], val);
    }
    __syncthreads();
    if (threadIdx.x < 90) atomicAdd(&g_mom[threadIdx.x], (double)blk[threadIdx.x]);
}

// ---------------------------------------------------------------------------
// 7) Per-channel BN stats from moments; fold BN into weights/bias
// ---------------------------------------------------------------------------
__global__ void stats_kernel(const float* __restrict__ weight, const float* __restrict__ bias,
                             const float* __restrict__ gamma, const float* __restrict__ beta) {
    int c = threadIdx.x;
    if (c >= COUT) return;

    double w[12];
    #pragma unroll
    for (int j = 0; j < 12; j++)
        w[j] = (double)weight[(j / 3) * (CIN * COUT) + (j % 3) * COUT + c];
    double b = (double)bias[c];

    double ws = 0.0;
    #pragma unroll
    for (int j = 0; j < 12; j++) ws += w[j] * g_mom[j];

    double wMw = 0.0;
    int idx = 12;
    #pragma unroll
    for (int f = 0; f < 12; f++) {
        #pragma unroll
        for (int g = f; g < 12; g++) {
            double mv = g_mom[idx++];
            wMw += ((f == g) ? 1.0 : 2.0) * w[f] * w[g] * mv;
        }
    }

    const double T = (double)NTOT;
    double mean  = (ws + T * b) / T;
    double sumsq = wMw + 2.0 * b * ws + T * b * b;
    double var   = sumsq / T - mean * mean;
    double a     = (double)gamma[c] / sqrt(var + 1e-5);

    #pragma unroll
    for (int j = 0; j < 12; j++) g_Wf[j * COUT + c] = (float)(w[j] * a);
    g_bf[c] = (float)((b - mean) * a + (double)beta[c]);
}

// ---------------------------------------------------------------------------
// 8) Final: out[b,c,n] = relu(t_i . w'_c + b'_c)
// ---------------------------------------------------------------------------
__global__ void __launch_bounds__(256) final_kernel(float* __restrict__ out) {
    __shared__ float sW[12][COUT];
    __shared__ float sb[COUT];
    int tid = threadIdx.y * 32 + threadIdx.x;
    for (int idx = tid; idx < 12 * COUT; idx += 256)
        sW[idx / COUT][idx % COUT] = g_Wf[idx];
    if (tid < COUT) sb[tid] = g_bf[tid];
    __syncthreads();

    int i = blockIdx.x * 32 + threadIdx.x;
    int b = i >> 15;
    int n = i & (NN - 1);

    float4 a0 = reinterpret_cast<const float4*>(g_T0)[i];
    float4 a1 = reinterpret_cast<const float4*>(g_T1)[i];
    float4 a2 = reinterpret_cast<const float4*>(g_T2)[i];
    float4 a3 = reinterpret_cast<const float4*>(g_T3)[i];
    float t[12] = {a0.x, a0.y, a0.z, a1.x, a1.y, a1.z,
                   a2.x, a2.y, a2.z, a3.x, a3.y, a3.z};

    float* ob = out + (size_t)b * COUT * NN + n;
    #pragma unroll
    for (int q = 0; q < 16; q++) {
        int c = q * 8 + threadIdx.y;
        float acc = sb[c];
        #pragma unroll
        for (int j = 0; j < 12; j++) acc = fmaf(t[j], sW[j][c], acc);
        ob[(size_t)c * NN] = fmaxf(acc, 0.f);
    }
}

// ---------------------------------------------------------------------------
extern "C" void kernel_launch(void* const* d_in, const int* in_sizes, int n_in,
                              void* d_out, int out_size) {
    const float* x      = (const float*)d_in[0];
    const int*   ei     = (const int*)d_in[1];
    const float* ew     = (const float*)d_in[2];
    const float* weight = (const float*)d_in[3];
    const float* bias   = (const float*)d_in[4];
    const float* gamma  = (const float*)d_in[5];
    const float* beta   = (const float*)d_in[6];
    float* out = (float*)d_out;
    (void)in_sizes; (void)n_in; (void)out_size;

    const int EB2 = NEDGE / 2 / 256;   // 8192  (2 edges/thread)
    const int EB4 = NEDGE / 4 / 256;   // 4096  (4 edges/thread)
    const int TB  = NTOT / 256;        // 1024

    setup_kernel<<<TB, 256>>>(x);             // T0, zero T1, deg, moments
    initT_kernel<2, 0><<<TB, 256>>>();        // T2 = -T0
    deg_kernel<<<EB2, 256>>>(ei, ew);
    dis_kernel<<<TB, 256>>>();

    // fused: nw + T1 += L_hat T0
    norm_prop_kernel<<<EB4, 256>>>(ei, ew);
    // T3 = -T1; T2 += 2 L_hat T1
    initT_kernel<3, 1><<<TB, 256>>>();
    prop_kernel<1, 2, 2><<<EB4, 256>>>(ei);
    // T3 += 2 L_hat T2
    prop_kernel<2, 3, 2><<<EB4, 256>>>(ei);

    moments_kernel<<<256, 256>>>();
    stats_kernel<<<1, 128>>>(weight, bias, gamma, beta);

    dim3 fb(32, 8);
    final_kernel<<<NTOT / 32, fb>>>(out);
}

// round 5
// speedup vs baseline: 1.1370x; 1.1370x over previous
#include <cuda_runtime.h>

#define NB    8
#define CIN   3
#define NN    32768
#define COUT  128
#define NEDGE 4194304
#define NTOT  262144   // NB * NN

__device__ float  g_T0[NTOT * 4];
__device__ float  g_T1[NTOT * 4];
__device__ float  g_T2[NTOT * 4];
__device__ float  g_T3[NTOT * 4];
__device__ float  g_U[NTOT * 4];      // dis-scaled gather source (reused per hop)
__device__ float  g_Z[NTOT * 4];      // accumulation target (reused per hop)
__device__ float  g_deg[NTOT];
__device__ float  g_dis[NTOT];
__device__ double g_mom[90];          // s[12] then upper-triangular M[78]
__device__ float  g_Wf[12 * COUT];    // BN-folded weights
__device__ float  g_bf[COUT];         // BN-folded bias

__device__ __forceinline__ void red_v4(float* addr, float a, float b, float c) {
    asm volatile("red.global.add.v4.f32 [%0], {%1, %2, %3, %4};"
                 :: "l"(addr), "f"(a), "f"(b), "f"(c), "f"(0.f) : "memory");
}

// ---------------------------------------------------------------------------
// 1) T0 = h (B,CIN,N)->(B*N,3 pad 4); zero Z, deg, moments
// ---------------------------------------------------------------------------
__global__ void setup_kernel(const float* __restrict__ x) {
    int i = blockIdx.x * blockDim.x + threadIdx.x;
    if (i < NTOT) {
        int b = i >> 15;          // NN = 2^15
        int n = i & (NN - 1);
        const float* xb = x + (size_t)b * CIN * NN + n;
        float4 v;
        v.x = xb[0];
        v.y = xb[NN];
        v.z = xb[2 * NN];
        v.w = 0.f;
        reinterpret_cast<float4*>(g_T0)[i] = v;
        reinterpret_cast<float4*>(g_Z)[i]  = make_float4(0.f, 0.f, 0.f, 0.f);
        g_deg[i] = 0.f;
    }
    if (blockIdx.x == 0 && threadIdx.x < 90) g_mom[threadIdx.x] = 0.0;
}

// ---------------------------------------------------------------------------
// 2) deg[src] += w  (self loops removed) — 2 edges/thread
// ---------------------------------------------------------------------------
__global__ void __launch_bounds__(256) deg_kernel(const int* __restrict__ ei,
                                                  const float* __restrict__ ew) {
    int base = (blockIdx.x * blockDim.x + threadIdx.x) * 2;
    int   s0 = ei[base],         s1 = ei[base + 1];
    int   d0 = ei[NEDGE + base], d1 = ei[NEDGE + base + 1];
    float w0 = ew[base],         w1 = ew[base + 1];
    if (s0 != d0 && w0 != 0.f) atomicAdd(&g_deg[s0], w0);
    if (s1 != d1 && w1 != 0.f) atomicAdd(&g_deg[s1], w1);
}

// ---------------------------------------------------------------------------
// 3) dis[i] = rsqrt(deg) (or 0);  U = dis * T0
// ---------------------------------------------------------------------------
__global__ void disU0_kernel() {
    int i = blockIdx.x * blockDim.x + threadIdx.x;
    if (i >= NTOT) return;
    float d = g_deg[i];
    float dis = (d > 0.f) ? rsqrtf(fmaxf(d, 1e-12f)) : 0.f;
    g_dis[i] = dis;
    float4 t = reinterpret_cast<const float4*>(g_T0)[i];
    reinterpret_cast<float4*>(g_U)[i] = make_float4(dis * t.x, dis * t.y, dis * t.z, 0.f);
}

// ---------------------------------------------------------------------------
// 4) Edge pass (identical all 3 hops): Z[d] += w * U[s]   (raw w, no dis!)
//    2 edges/thread
// ---------------------------------------------------------------------------
__global__ void __launch_bounds__(256) edge_kernel(const int* __restrict__ ei,
                                                   const float* __restrict__ ew) {
    int base = (blockIdx.x * blockDim.x + threadIdx.x) * 2;
    int   s0 = ei[base],         s1 = ei[base + 1];
    int   d0 = ei[NEDGE + base], d1 = ei[NEDGE + base + 1];
    float w0 = ew[base],         w1 = ew[base + 1];
    float4 u0 = __ldg(reinterpret_cast<const float4*>(g_U) + s0);
    float4 u1 = __ldg(reinterpret_cast<const float4*>(g_U) + s1);
    if (s0 != d0 && w0 != 0.f)
        red_v4(g_Z + 4 * (size_t)d0, w0 * u0.x, w0 * u0.y, w0 * u0.z);
    if (s1 != d1 && w1 != 0.f)
        red_v4(g_Z + 4 * (size_t)d1, w1 * u1.x, w1 * u1.y, w1 * u1.z);
}

// ---------------------------------------------------------------------------
// 5) Node epilogues (fold the Chebyshev recursion + dst-side dis scale)
//    epi1: T1 = -dis*Z;           U = dis*T1;  Z = 0
//    epi2: T2 = -2*dis*Z - T0;    U = dis*T2;  Z = 0
//    epi3: T3 = -2*dis*Z - T1
// ---------------------------------------------------------------------------
__global__ void epi1_kernel() {
    int i = blockIdx.x * blockDim.x + threadIdx.x;
    if (i >= NTOT) return;
    float dis = g_dis[i];
    float4 z = reinterpret_cast<const float4*>(g_Z)[i];
    float4 t = make_float4(-dis * z.x, -dis * z.y, -dis * z.z, 0.f);
    reinterpret_cast<float4*>(g_T1)[i] = t;
    reinterpret_cast<float4*>(g_U)[i]  = make_float4(dis * t.x, dis * t.y, dis * t.z, 0.f);
    reinterpret_cast<float4*>(g_Z)[i]  = make_float4(0.f, 0.f, 0.f, 0.f);
}

__global__ void epi2_kernel() {
    int i = blockIdx.x * blockDim.x + threadIdx.x;
    if (i >= NTOT) return;
    float dis = g_dis[i];
    float4 z  = reinterpret_cast<const float4*>(g_Z)[i];
    float4 t0 = reinterpret_cast<const float4*>(g_T0)[i];
    float m = -2.f * dis;
    float4 t = make_float4(fmaf(m, z.x, -t0.x), fmaf(m, z.y, -t0.y), fmaf(m, z.z, -t0.z), 0.f);
    reinterpret_cast<float4*>(g_T2)[i] = t;
    reinterpret_cast<float4*>(g_U)[i]  = make_float4(dis * t.x, dis * t.y, dis * t.z, 0.f);
    reinterpret_cast<float4*>(g_Z)[i]  = make_float4(0.f, 0.f, 0.f, 0.f);
}

__global__ void epi3_kernel() {
    int i = blockIdx.x * blockDim.x + threadIdx.x;
    if (i >= NTOT) return;
    float dis = g_dis[i];
    float4 z  = reinterpret_cast<const float4*>(g_Z)[i];
    float4 t1 = reinterpret_cast<const float4*>(g_T1)[i];
    float m = -2.f * dis;
    reinterpret_cast<float4*>(g_T3)[i] =
        make_float4(fmaf(m, z.x, -t1.x), fmaf(m, z.y, -t1.y), fmaf(m, z.z, -t1.z), 0.f);
}

// ---------------------------------------------------------------------------
// 6) Moments: s[12] = sum t,  M[78] = upper-tri of sum t t^T
// ---------------------------------------------------------------------------
__device__ __forceinline__ float warp_sum(float v) {
    #pragma unroll
    for (int o = 16; o > 0; o >>= 1) v += __shfl_down_sync(0xFFFFFFFFu, v, o);
    return v;
}

__global__ void __launch_bounds__(256) moments_kernel() {
    float s[12];
    float m[78];
    #pragma unroll
    for (int j = 0; j < 12; j++) s[j] = 0.f;
    #pragma unroll
    for (int j = 0; j < 78; j++) m[j] = 0.f;

    int stride = gridDim.x * blockDim.x;
    for (int i = blockIdx.x * blockDim.x + threadIdx.x; i < NTOT; i += stride) {
        float4 a = reinterpret_cast<const float4*>(g_T0)[i];
        float4 b = reinterpret_cast<const float4*>(g_T1)[i];
        float4 c = reinterpret_cast<const float4*>(g_T2)[i];
        float4 d = reinterpret_cast<const float4*>(g_T3)[i];
        float t[12] = {a.x, a.y, a.z, b.x, b.y, b.z, c.x, c.y, c.z, d.x, d.y, d.z};
        #pragma unroll
        for (int f = 0; f < 12; f++) s[f] += t[f];
        int idx = 0;
        #pragma unroll
        for (int f = 0; f < 12; f++) {
            #pragma unroll
            for (int g = f; g < 12; g++) {
                m[idx] += t[f] * t[g];
                idx++;
            }
        }
    }

    __shared__ float blk[90];
    if (threadIdx.x < 90) blk[threadIdx.x] = 0.f;
    __syncthreads();
    #pragma unroll
    for (int v = 0; v < 12; v++) {
        float val = warp_sum(s[v]);
        if ((threadIdx.x & 31) == 0) atomicAdd(&blk[v], val);
    }
    #pragma unroll
    for (int v = 0; v < 78; v++) {
        float val = warp_sum(m[v]);
        if ((threadIdx.x & 31) == 0) atomicAdd(&blk[12 + v], val);
    }
    __syncthreads();
    if (threadIdx.x < 90) atomicAdd(&g_mom[threadIdx.x], (double)blk[threadIdx.x]);
}

// ---------------------------------------------------------------------------
// 7) Per-channel BN stats from moments; fold BN into weights/bias
// ---------------------------------------------------------------------------
__global__ void stats_kernel(const float* __restrict__ weight, const float* __restrict__ bias,
                             const float* __restrict__ gamma, const float* __restrict__ beta) {
    int c = threadIdx.x;
    if (c >= COUT) return;

    double w[12];
    #pragma unroll
    for (int j = 0; j < 12; j++)
        w[j] = (double)weight[(j / 3) * (CIN * COUT) + (j % 3) * COUT + c];
    double b = (double)bias[c];

    double ws = 0.0;
    #pragma unroll
    for (int j = 0; j < 12; j++) ws += w[j] * g_mom[j];

    double wMw = 0.0;
    int idx = 12;
    #pragma unroll
    for (int f = 0; f < 12; f++) {
        #pragma unroll
        for (int g = f; g < 12; g++) {
            double mv = g_mom[idx++];
            wMw += ((f == g) ? 1.0 : 2.0) * w[f] * w[g] * mv;
        }
    }

    const double T = (double)NTOT;
    double mean  = (ws + T * b) / T;
    double sumsq = wMw + 2.0 * b * ws + T * b * b;
    double var   = sumsq / T - mean * mean;
    double a     = (double)gamma[c] / sqrt(var + 1e-5);

    #pragma unroll
    for (int j = 0; j < 12; j++) g_Wf[j * COUT + c] = (float)(w[j] * a);
    g_bf[c] = (float)((b - mean) * a + (double)beta[c]);
}

// ---------------------------------------------------------------------------
// 8) Final: out[b,c,n] = relu(t_i . w'_c + b'_c)
// ---------------------------------------------------------------------------
__global__ void __launch_bounds__(256) final_kernel(float* __restrict__ out) {
    __shared__ float sW[12][COUT];
    __shared__ float sb[COUT];
    int tid = threadIdx.y * 32 + threadIdx.x;
    for (int idx = tid; idx < 12 * COUT; idx += 256)
        sW[idx / COUT][idx % COUT] = g_Wf[idx];
    if (tid < COUT) sb[tid] = g_bf[tid];
    __syncthreads();

    int i = blockIdx.x * 32 + threadIdx.x;
    int b = i >> 15;
    int n = i & (NN - 1);

    float4 a0 = reinterpret_cast<const float4*>(g_T0)[i];
    float4 a1 = reinterpret_cast<const float4*>(g_T1)[i];
    float4 a2 = reinterpret_cast<const float4*>(g_T2)[i];
    float4 a3 = reinterpret_cast<const float4*>(g_T3)[i];
    float t[12] = {a0.x, a0.y, a0.z, a1.x, a1.y, a1.z,
                   a2.x, a2.y, a2.z, a3.x, a3.y, a3.z};

    float* ob = out + (size_t)b * COUT * NN + n;
    #pragma unroll
    for (int q = 0; q < 16; q++) {
        int c = q * 8 + threadIdx.y;
        float acc = sb[c];
        #pragma unroll
        for (int j = 0; j < 12; j++) acc = fmaf(t[j], sW[j][c], acc);
        ob[(size_t)c * NN] = fmaxf(acc, 0.f);
    }
}

// ---------------------------------------------------------------------------
extern "C" void kernel_launch(void* const* d_in, const int* in_sizes, int n_in,
                              void* d_out, int out_size) {
    const float* x      = (const float*)d_in[0];
    const int*   ei     = (const int*)d_in[1];
    const float* ew     = (const float*)d_in[2];
    const float* weight = (const float*)d_in[3];
    const float* bias   = (const float*)d_in[4];
    const float* gamma  = (const float*)d_in[5];
    const float* beta   = (const float*)d_in[6];
    float* out = (float*)d_out;
    (void)in_sizes; (void)n_in; (void)out_size;

    const int EB2 = NEDGE / 2 / 256;   // 8192  (2 edges/thread)
    const int TB  = NTOT / 256;        // 1024

    setup_kernel<<<TB, 256>>>(x);      // T0, zero Z, deg, moments
    deg_kernel<<<EB2, 256>>>(ei, ew);
    disU0_kernel<<<TB, 256>>>();       // dis + U = dis*T0

    edge_kernel<<<EB2, 256>>>(ei, ew); // Z = A U0
    epi1_kernel<<<TB, 256>>>();        // T1, U1, Z=0
    edge_kernel<<<EB2, 256>>>(ei, ew); // Z = A U1
    epi2_kernel<<<TB, 256>>>();        // T2, U2, Z=0
    edge_kernel<<<EB2, 256>>>(ei, ew); // Z = A U2
    epi3_kernel<<<TB, 256>>>();        // T3

    moments_kernel<<<256, 256>>>();
    stats_kernel<<<1, 128>>>(weight, bias, gamma, beta);

    dim3 fb(32, 8);
    final_kernel<<<NTOT / 32, fb>>>(out);
}